// round 17
// baseline (speedup 1.0000x reference)
#include <cuda_runtime.h>
#include <math.h>

#define N_NODES 100000
#define E_EDGES 800000
#define G_GRAPHS 512
#define HID 32
#define D_CUT 5.0f
#define TAB 8192
#define NODE_BLOCKS 1563  // ceil(100000/64)
#define EDGE_TILES 12500  // 800000/64

typedef unsigned long long u64;

// ---------------- scratch (static, no allocation) ----------------
__device__ __align__(16) float g_ss[G_GRAPHS * 64];
__device__ __align__(16) float g_xm[N_NODES * 32];
__device__ __align__(16) float g_a[N_NODES * 32];
__device__ __align__(16) float g_b[N_NODES * 32];
__device__ __align__(16) float g_gate[N_NODES * 32];
__device__ __align__(16) float g_macc[N_NODES * 32];
__device__ __align__(16) float g_pacc[N_NODES * 4];
__device__ __align__(16) float4 g_pos4[N_NODES];
__device__ __align__(16) float g_tab[TAB * 32];

// tanh-based activations: 1 MUFU + 2 FFMA
__device__ __forceinline__ float tanha(float x) {
    float y; asm("tanh.approx.f32 %0, %1;" : "=f"(y) : "f"(x)); return y;
}
__device__ __forceinline__ float siluf(float v) {
    return v * (0.5f * tanha(0.5f * v) + 0.5f);
}
__device__ __forceinline__ float sigmf(float v) {
    return 0.5f * tanha(0.5f * v) + 0.5f;
}
__device__ __forceinline__ float siluf_p(float v) { return v / (1.0f + __expf(-v)); }

__device__ __forceinline__ void red_v4(float* p, float a, float b, float c, float d) {
    asm volatile("red.global.add.v4.f32 [%0], {%1,%2,%3,%4};"
                 :: "l"(p), "f"(a), "f"(b), "f"(c), "f"(d) : "memory");
}

__device__ __forceinline__ u64 pack2(float lo, float hi) {
    u64 r; asm("mov.b64 %0, {%1, %2};" : "=l"(r) : "f"(lo), "f"(hi)); return r;
}
__device__ __forceinline__ void unpack2(u64 v, float& lo, float& hi) {
    asm("mov.b64 {%0, %1}, %2;" : "=f"(lo), "=f"(hi) : "l"(v));
}
__device__ __forceinline__ void ffma2(u64& d, u64 a, u64 b) {
    asm("fma.rn.f32x2 %0, %1, %2, %0;" : "+l"(d) : "l"(a), "l"(b));
}

// ---------------- K1: time MLP + dist_emb table (fused) ----------------
__global__ void __launch_bounds__(256) k_time(
        const float* __restrict__ time,
        const float* __restrict__ w1, const float* __restrict__ b1,
        const float* __restrict__ w2, const float* __restrict__ b2,
        const float* __restrict__ means, const float* __restrict__ betas,
        const float* __restrict__ w_dist) {
    int tid = threadIdx.x;
    if (blockIdx.x >= G_GRAPHS / 4) {
        __shared__ float sW[1024];
        __shared__ float sMu[32], sBeta[32];
        for (int k = tid; k < 1024; k += 256) sW[k] = w_dist[k];
        if (tid < 32) { sMu[tid] = means[tid]; sBeta[tid] = betas[tid]; }
        __syncthreads();
        int r = (blockIdx.x - G_GRAPHS / 4) * 8 + (tid >> 5);
        int c = tid & 31;
        float d = (float)r * (D_CUT / (float)(TAB - 1));
        float cutoff = 0.5f * (__cosf(d * (3.14159265358979f / D_CUT)) + 1.0f);
        float ed = __expf(-d);
        float acc = 0.0f;
        #pragma unroll 8
        for (int k = 0; k < 32; k++) {
            float t = ed - sMu[k];
            acc += __expf(-sBeta[k] * t * t) * sW[k * 32 + c];
        }
        g_tab[r * 32 + c] = cutoff * acc;
        return;
    }
    __shared__ float trow[4][128];
    __shared__ float hid[4][64];
    int gsub = tid >> 6;
    int t = tid & 63;
    int g = blockIdx.x * 4 + gsub;
    trow[gsub][t]      = time[g * 128 + t];
    trow[gsub][t + 64] = time[g * 128 + 64 + t];
    __syncthreads();
    float acc = b1[t];
    #pragma unroll 8
    for (int k = 0; k < 128; k++) acc += trow[gsub][k] * w1[k * 64 + t];
    hid[gsub][t] = siluf_p(acc);
    __syncthreads();
    float acc2 = b2[t];
    #pragma unroll 8
    for (int k = 0; k < 64; k++) acc2 += hid[gsub][k] * w2[k * 64 + t];
    g_ss[g * 64 + t] = acc2;
}

// ---------------- K2: per-node precompute, 8 lanes x NE=4 (non-persistent) --
__global__ void __launch_bounds__(128) k_node(
        const float* __restrict__ x, const int* __restrict__ batch,
        const float* __restrict__ pos,
        const float* __restrict__ msg_w1, const float* __restrict__ msg_b1,
        const float* __restrict__ gate_w, const float* __restrict__ gate_b) {
    __shared__ __align__(16) float sW1[64 * 32];
    __shared__ __align__(16) float sWg[32 * 32];
    int tid = threadIdx.x;
    for (int k = tid; k < 2048; k += 128) sW1[k] = msg_w1[k];
    for (int k = tid; k < 1024; k += 128) sWg[k] = gate_w[k];
    __syncthreads();

    int q = tid & 7;
    int c0 = q * 4;
    int n0 = blockIdx.x * 64 + (tid >> 3) * 4;
    if (n0 >= N_NODES) return;   // warp-uniform: 16 nodes/warp, 16 | 100000

    float xmA[4], xmB[4], xmC[4], xmD[4];
    {
        int bn = batch[n0];
        float4 sc = *(const float4*)&g_ss[bn * 64 + c0];
        float4 sh = *(const float4*)&g_ss[bn * 64 + 32 + c0];
        float4 xv = *(const float4*)&x[n0 * 32 + c0];
        xmA[0] = siluf(xv.x * (1.0f + sc.x) + sh.x);
        xmA[1] = siluf(xv.y * (1.0f + sc.y) + sh.y);
        xmA[2] = siluf(xv.z * (1.0f + sc.z) + sh.z);
        xmA[3] = siluf(xv.w * (1.0f + sc.w) + sh.w);
    }
    {
        int bn = batch[n0 + 1];
        float4 sc = *(const float4*)&g_ss[bn * 64 + c0];
        float4 sh = *(const float4*)&g_ss[bn * 64 + 32 + c0];
        float4 xv = *(const float4*)&x[(n0 + 1) * 32 + c0];
        xmB[0] = siluf(xv.x * (1.0f + sc.x) + sh.x);
        xmB[1] = siluf(xv.y * (1.0f + sc.y) + sh.y);
        xmB[2] = siluf(xv.z * (1.0f + sc.z) + sh.z);
        xmB[3] = siluf(xv.w * (1.0f + sc.w) + sh.w);
    }
    {
        int bn = batch[n0 + 2];
        float4 sc = *(const float4*)&g_ss[bn * 64 + c0];
        float4 sh = *(const float4*)&g_ss[bn * 64 + 32 + c0];
        float4 xv = *(const float4*)&x[(n0 + 2) * 32 + c0];
        xmC[0] = siluf(xv.x * (1.0f + sc.x) + sh.x);
        xmC[1] = siluf(xv.y * (1.0f + sc.y) + sh.y);
        xmC[2] = siluf(xv.z * (1.0f + sc.z) + sh.z);
        xmC[3] = siluf(xv.w * (1.0f + sc.w) + sh.w);
    }
    {
        int bn = batch[n0 + 3];
        float4 sc = *(const float4*)&g_ss[bn * 64 + c0];
        float4 sh = *(const float4*)&g_ss[bn * 64 + 32 + c0];
        float4 xv = *(const float4*)&x[(n0 + 3) * 32 + c0];
        xmD[0] = siluf(xv.x * (1.0f + sc.x) + sh.x);
        xmD[1] = siluf(xv.y * (1.0f + sc.y) + sh.y);
        xmD[2] = siluf(xv.z * (1.0f + sc.z) + sh.z);
        xmD[3] = siluf(xv.w * (1.0f + sc.w) + sh.w);
    }

    u64 aA[2], aB[2], aC[2], aD[2];
    u64 bA[2], bB[2], bC[2], bD[2];
    u64 gA[2], gB[2], gC[2], gD[2];
    {
        u64 m0 = pack2(msg_b1[c0], msg_b1[c0 + 1]);
        u64 m1 = pack2(msg_b1[c0 + 2], msg_b1[c0 + 3]);
        u64 g0 = pack2(gate_b[c0], gate_b[c0 + 1]);
        u64 g1 = pack2(gate_b[c0 + 2], gate_b[c0 + 3]);
        aA[0] = m0; aA[1] = m1; aB[0] = m0; aB[1] = m1;
        aC[0] = m0; aC[1] = m1; aD[0] = m0; aD[1] = m1;
        bA[0] = 0; bA[1] = 0; bB[0] = 0; bB[1] = 0;
        bC[0] = 0; bC[1] = 0; bD[0] = 0; bD[1] = 0;
        gA[0] = g0; gA[1] = g1; gB[0] = g0; gB[1] = g1;
        gC[0] = g0; gC[1] = g1; gD[0] = g0; gD[1] = g1;
    }
    #pragma unroll
    for (int kk = 0; kk < 32; kk++) {
        float vA = __shfl_sync(0xffffffffu, xmA[kk & 3], kk >> 2, 8);
        float vB = __shfl_sync(0xffffffffu, xmB[kk & 3], kk >> 2, 8);
        float vC = __shfl_sync(0xffffffffu, xmC[kk & 3], kk >> 2, 8);
        float vD = __shfl_sync(0xffffffffu, xmD[kk & 3], kk >> 2, 8);
        u64 vvA = pack2(vA, vA), vvB = pack2(vB, vB);
        u64 vvC = pack2(vC, vC), vvD = pack2(vD, vD);
        ulonglong2 wa = *(const ulonglong2*)&sW1[kk * 32 + c0];
        ulonglong2 wb = *(const ulonglong2*)&sW1[(32 + kk) * 32 + c0];
        ulonglong2 wg = *(const ulonglong2*)&sWg[kk * 32 + c0];
        ffma2(aA[0], wa.x, vvA); ffma2(aA[1], wa.y, vvA);
        ffma2(aB[0], wa.x, vvB); ffma2(aB[1], wa.y, vvB);
        ffma2(aC[0], wa.x, vvC); ffma2(aC[1], wa.y, vvC);
        ffma2(aD[0], wa.x, vvD); ffma2(aD[1], wa.y, vvD);
        ffma2(bA[0], wb.x, vvA); ffma2(bA[1], wb.y, vvA);
        ffma2(bB[0], wb.x, vvB); ffma2(bB[1], wb.y, vvB);
        ffma2(bC[0], wb.x, vvC); ffma2(bC[1], wb.y, vvC);
        ffma2(bD[0], wb.x, vvD); ffma2(bD[1], wb.y, vvD);
        ffma2(gA[0], wg.x, vvA); ffma2(gA[1], wg.y, vvA);
        ffma2(gB[0], wg.x, vvB); ffma2(gB[1], wg.y, vvB);
        ffma2(gC[0], wg.x, vvC); ffma2(gC[1], wg.y, vvC);
        ffma2(gD[0], wg.x, vvD); ffma2(gD[1], wg.y, vvD);
    }

    float4 z = make_float4(0.f, 0.f, 0.f, 0.f);
    {
        *(float4*)&g_xm[n0 * 32 + c0] = make_float4(xmA[0], xmA[1], xmA[2], xmA[3]);
        *(ulonglong2*)&g_a[n0 * 32 + c0] = make_ulonglong2(aA[0], aA[1]);
        *(ulonglong2*)&g_b[n0 * 32 + c0] = make_ulonglong2(bA[0], bA[1]);
        float t0, t1, t2, t3;
        unpack2(gA[0], t0, t1); unpack2(gA[1], t2, t3);
        *(float4*)&g_gate[n0 * 32 + c0] =
            make_float4(sigmf(t0), sigmf(t1), sigmf(t2), sigmf(t3));
        *(float4*)&g_macc[n0 * 32 + c0] = z;
    }
    {
        int n = n0 + 1;
        *(float4*)&g_xm[n * 32 + c0] = make_float4(xmB[0], xmB[1], xmB[2], xmB[3]);
        *(ulonglong2*)&g_a[n * 32 + c0] = make_ulonglong2(aB[0], aB[1]);
        *(ulonglong2*)&g_b[n * 32 + c0] = make_ulonglong2(bB[0], bB[1]);
        float t0, t1, t2, t3;
        unpack2(gB[0], t0, t1); unpack2(gB[1], t2, t3);
        *(float4*)&g_gate[n * 32 + c0] =
            make_float4(sigmf(t0), sigmf(t1), sigmf(t2), sigmf(t3));
        *(float4*)&g_macc[n * 32 + c0] = z;
    }
    {
        int n = n0 + 2;
        *(float4*)&g_xm[n * 32 + c0] = make_float4(xmC[0], xmC[1], xmC[2], xmC[3]);
        *(ulonglong2*)&g_a[n * 32 + c0] = make_ulonglong2(aC[0], aC[1]);
        *(ulonglong2*)&g_b[n * 32 + c0] = make_ulonglong2(bC[0], bC[1]);
        float t0, t1, t2, t3;
        unpack2(gC[0], t0, t1); unpack2(gC[1], t2, t3);
        *(float4*)&g_gate[n * 32 + c0] =
            make_float4(sigmf(t0), sigmf(t1), sigmf(t2), sigmf(t3));
        *(float4*)&g_macc[n * 32 + c0] = z;
    }
    {
        int n = n0 + 3;
        *(float4*)&g_xm[n * 32 + c0] = make_float4(xmD[0], xmD[1], xmD[2], xmD[3]);
        *(ulonglong2*)&g_a[n * 32 + c0] = make_ulonglong2(aD[0], aD[1]);
        *(ulonglong2*)&g_b[n * 32 + c0] = make_ulonglong2(bD[0], bD[1]);
        float t0, t1, t2, t3;
        unpack2(gD[0], t0, t1); unpack2(gD[1], t2, t3);
        *(float4*)&g_gate[n * 32 + c0] =
            make_float4(sigmf(t0), sigmf(t1), sigmf(t2), sigmf(t3));
        *(float4*)&g_macc[n * 32 + c0] = z;
    }
    if (q < 4) {
        int n = n0 + q;
        *(float4*)&g_pacc[n * 4] = z;
        g_pos4[n] = make_float4(pos[n * 3], pos[n * 3 + 1], pos[n * 3 + 2], 0.0f);
    }
}

// ---------------- K3: edge kernel, persistent, 8 lanes/group x NE=4 ---------
// pos gathers + dist + table index computed only on lanes q<4 (dedup);
// next tile's edge indices prefetched to overlap index-load latency.
#define MV32X4(aA, aB, aC, aD, iA_, iB_, iC_, iD_, W, c0)                        \
    do {                                                                         \
        _Pragma("unroll")                                                        \
        for (int kk = 0; kk < 32; kk++) {                                        \
            float vA = __shfl_sync(0xffffffffu, iA_[kk & 3], kk >> 2, 8);        \
            float vB = __shfl_sync(0xffffffffu, iB_[kk & 3], kk >> 2, 8);        \
            float vC = __shfl_sync(0xffffffffu, iC_[kk & 3], kk >> 2, 8);        \
            float vD = __shfl_sync(0xffffffffu, iD_[kk & 3], kk >> 2, 8);        \
            u64 vvA = pack2(vA, vA), vvB = pack2(vB, vB);                        \
            u64 vvC = pack2(vC, vC), vvD = pack2(vD, vD);                        \
            ulonglong2 w = *(const ulonglong2*)&W[kk * 32 + c0];                 \
            ffma2(aA[0], w.x, vvA); ffma2(aA[1], w.y, vvA);                      \
            ffma2(aB[0], w.x, vvB); ffma2(aB[1], w.y, vvB);                      \
            ffma2(aC[0], w.x, vvC); ffma2(aC[1], w.y, vvC);                      \
            ffma2(aD[0], w.x, vvD); ffma2(aD[1], w.y, vvD);                      \
        }                                                                        \
    } while (0)

__global__ void __launch_bounds__(128) k_edge(
        const int* __restrict__ ei,
        const float* __restrict__ msg_w2, const float* __restrict__ msg_b2,
        const float* __restrict__ coord_w1, const float* __restrict__ coord_b1,
        const float* __restrict__ coord_w2, const float* __restrict__ coord_b2) {
    __shared__ __align__(16) float sW2[1024];
    __shared__ __align__(16) float sC1[1024];
    __shared__ float sC2[32], sB2[32], sCB1[32];
    __shared__ float sCB2;

    int tid = threadIdx.x;
    for (int k = tid; k < 1024; k += 128) {
        sW2[k] = msg_w2[k];
        sC1[k] = coord_w1[k];
    }
    if (tid < 32) {
        sC2[tid]  = coord_w2[tid];
        sB2[tid]  = msg_b2[tid];
        sCB1[tid] = coord_b1[tid];
    }
    if (tid == 0) sCB2 = coord_b2[0];
    __syncthreads();

    int q = tid & 7;
    int c0 = q * 4;
    int lane_e = (tid >> 3) * 4;

    u64 mb0 = pack2(sB2[c0], sB2[c0 + 1]);
    u64 mb1 = pack2(sB2[c0 + 2], sB2[c0 + 3]);
    u64 cb0 = pack2(sCB1[c0], sCB1[c0 + 1]);
    u64 cb1v = pack2(sCB1[c0 + 2], sCB1[c0 + 3]);
    float w0 = sC2[c0], w1 = sC2[c0 + 1], w2 = sC2[c0 + 2], w3 = sC2[c0 + 3];
    float cb2s = sCB2;

    // prefetch first tile's indices
    int tile = blockIdx.x;
    int4 iv = *(const int4*)&ei[tile * 64 + lane_e];
    int4 jv = *(const int4*)&ei[E_EDGES + tile * 64 + lane_e];

    for (; tile < EDGE_TILES; tile += gridDim.x) {
        int4 iv_c = iv, jv_c = jv;
        int nt = tile + gridDim.x;
        if (nt < EDGE_TILES) {
            iv = *(const int4*)&ei[nt * 64 + lane_e];
            jv = *(const int4*)&ei[E_EDGES + nt * 64 + lane_e];
        }

        int eq = q & 3;
        int i_own = (eq & 2) ? ((eq & 1) ? iv_c.w : iv_c.z)
                             : ((eq & 1) ? iv_c.y : iv_c.x);
        int j_own = (eq & 2) ? ((eq & 1) ? jv_c.w : jv_c.z)
                             : ((eq & 1) ? jv_c.y : jv_c.x);

        // pos/dist only on lanes 0-3 of each group (dedup gathers)
        float dx = 0.f, dy = 0.f, dz = 0.f;
        int i0_own = 0;
        if (q < 4) {
            float4 pi = g_pos4[i_own], pj = g_pos4[j_own];
            dx = pi.x - pj.x; dy = pi.y - pj.y; dz = pi.z - pj.z;
            float dist = sqrtf(dx * dx + dy * dy + dz * dz);
            float u = fminf(dist, D_CUT) * ((float)(TAB - 1) / D_CUT);
            i0_own = min((int)(u + 0.5f), TAB - 1);
        }

        int i0A = __shfl_sync(0xffffffffu, i0_own, 0, 8);
        int i0B = __shfl_sync(0xffffffffu, i0_own, 1, 8);
        int i0C = __shfl_sync(0xffffffffu, i0_own, 2, 8);
        int i0D = __shfl_sync(0xffffffffu, i0_own, 3, 8);

        float hA[4], egA[4], hB[4], egB[4], hC[4], egC[4], hD[4], egD[4];
        {
            float4 a = *(const float4*)&g_a[iv_c.x * 32 + c0];
            float4 b = *(const float4*)&g_b[jv_c.x * 32 + c0];
            float4 t = *(const float4*)&g_tab[i0A * 32 + c0];
            float4 g = *(const float4*)&g_gate[jv_c.x * 32 + c0];
            hA[0] = siluf(a.x + b.x); hA[1] = siluf(a.y + b.y);
            hA[2] = siluf(a.z + b.z); hA[3] = siluf(a.w + b.w);
            egA[0] = t.x * g.x; egA[1] = t.y * g.y;
            egA[2] = t.z * g.z; egA[3] = t.w * g.w;
        }
        {
            float4 a = *(const float4*)&g_a[iv_c.y * 32 + c0];
            float4 b = *(const float4*)&g_b[jv_c.y * 32 + c0];
            float4 t = *(const float4*)&g_tab[i0B * 32 + c0];
            float4 g = *(const float4*)&g_gate[jv_c.y * 32 + c0];
            hB[0] = siluf(a.x + b.x); hB[1] = siluf(a.y + b.y);
            hB[2] = siluf(a.z + b.z); hB[3] = siluf(a.w + b.w);
            egB[0] = t.x * g.x; egB[1] = t.y * g.y;
            egB[2] = t.z * g.z; egB[3] = t.w * g.w;
        }
        {
            float4 a = *(const float4*)&g_a[iv_c.z * 32 + c0];
            float4 b = *(const float4*)&g_b[jv_c.z * 32 + c0];
            float4 t = *(const float4*)&g_tab[i0C * 32 + c0];
            float4 g = *(const float4*)&g_gate[jv_c.z * 32 + c0];
            hC[0] = siluf(a.x + b.x); hC[1] = siluf(a.y + b.y);
            hC[2] = siluf(a.z + b.z); hC[3] = siluf(a.w + b.w);
            egC[0] = t.x * g.x; egC[1] = t.y * g.y;
            egC[2] = t.z * g.z; egC[3] = t.w * g.w;
        }
        {
            float4 a = *(const float4*)&g_a[iv_c.w * 32 + c0];
            float4 b = *(const float4*)&g_b[jv_c.w * 32 + c0];
            float4 t = *(const float4*)&g_tab[i0D * 32 + c0];
            float4 g = *(const float4*)&g_gate[jv_c.w * 32 + c0];
            hD[0] = siluf(a.x + b.x); hD[1] = siluf(a.y + b.y);
            hD[2] = siluf(a.z + b.z); hD[3] = siluf(a.w + b.w);
            egD[0] = t.x * g.x; egD[1] = t.y * g.y;
            egD[2] = t.z * g.z; egD[3] = t.w * g.w;
        }

        u64 mmA[2], mmB[2], mmC[2], mmD[2];
        mmA[0] = mb0; mmA[1] = mb1; mmB[0] = mb0; mmB[1] = mb1;
        mmC[0] = mb0; mmC[1] = mb1; mmD[0] = mb0; mmD[1] = mb1;
        MV32X4(mmA, mmB, mmC, mmD, hA, hB, hC, hD, sW2, c0);

        float mA[4], mB[4], mC[4], mD[4];
        {
            float t0, t1;
            unpack2(mmA[0], t0, t1); mA[0] = siluf(t0) * egA[0]; mA[1] = siluf(t1) * egA[1];
            unpack2(mmA[1], t0, t1); mA[2] = siluf(t0) * egA[2]; mA[3] = siluf(t1) * egA[3];
            unpack2(mmB[0], t0, t1); mB[0] = siluf(t0) * egB[0]; mB[1] = siluf(t1) * egB[1];
            unpack2(mmB[1], t0, t1); mB[2] = siluf(t0) * egB[2]; mB[3] = siluf(t1) * egB[3];
            unpack2(mmC[0], t0, t1); mC[0] = siluf(t0) * egC[0]; mC[1] = siluf(t1) * egC[1];
            unpack2(mmC[1], t0, t1); mC[2] = siluf(t0) * egC[2]; mC[3] = siluf(t1) * egC[3];
            unpack2(mmD[0], t0, t1); mD[0] = siluf(t0) * egD[0]; mD[1] = siluf(t1) * egD[1];
            unpack2(mmD[1], t0, t1); mD[2] = siluf(t0) * egD[2]; mD[3] = siluf(t1) * egD[3];
        }

        red_v4(&g_macc[jv_c.x * 32 + c0], mA[0], mA[1], mA[2], mA[3]);
        red_v4(&g_macc[jv_c.y * 32 + c0], mB[0], mB[1], mB[2], mB[3]);
        red_v4(&g_macc[jv_c.z * 32 + c0], mC[0], mC[1], mC[2], mC[3]);
        red_v4(&g_macc[jv_c.w * 32 + c0], mD[0], mD[1], mD[2], mD[3]);

        u64 stA[2], stB[2], stC[2], stD[2];
        stA[0] = cb0; stA[1] = cb1v; stB[0] = cb0; stB[1] = cb1v;
        stC[0] = cb0; stC[1] = cb1v; stD[0] = cb0; stD[1] = cb1v;
        MV32X4(stA, stB, stC, stD, mA, mB, mC, mD, sC1, c0);

        float spA, spB, spC, spD;
        {
            float t0, t1, t2, t3;
            unpack2(stA[0], t0, t1); unpack2(stA[1], t2, t3);
            spA = siluf(t0) * w0 + siluf(t1) * w1 + siluf(t2) * w2 + siluf(t3) * w3;
            unpack2(stB[0], t0, t1); unpack2(stB[1], t2, t3);
            spB = siluf(t0) * w0 + siluf(t1) * w1 + siluf(t2) * w2 + siluf(t3) * w3;
            unpack2(stC[0], t0, t1); unpack2(stC[1], t2, t3);
            spC = siluf(t0) * w0 + siluf(t1) * w1 + siluf(t2) * w2 + siluf(t3) * w3;
            unpack2(stD[0], t0, t1); unpack2(stD[1], t2, t3);
            spD = siluf(t0) * w0 + siluf(t1) * w1 + siluf(t2) * w2 + siluf(t3) * w3;
        }
        spA += __shfl_xor_sync(0xffffffffu, spA, 1);
        spA += __shfl_xor_sync(0xffffffffu, spA, 2);
        spA += __shfl_xor_sync(0xffffffffu, spA, 4);
        spB += __shfl_xor_sync(0xffffffffu, spB, 1);
        spB += __shfl_xor_sync(0xffffffffu, spB, 2);
        spB += __shfl_xor_sync(0xffffffffu, spB, 4);
        spC += __shfl_xor_sync(0xffffffffu, spC, 1);
        spC += __shfl_xor_sync(0xffffffffu, spC, 2);
        spC += __shfl_xor_sync(0xffffffffu, spC, 4);
        spD += __shfl_xor_sync(0xffffffffu, spD, 1);
        spD += __shfl_xor_sync(0xffffffffu, spD, 2);
        spD += __shfl_xor_sync(0xffffffffu, spD, 4);

        if (q < 4) {
            float s_own = (q & 2) ? ((q & 1) ? spD : spC) : ((q & 1) ? spB : spA);
            s_own += cb2s;
            red_v4(&g_pacc[j_own * 4], dx * s_own, dy * s_own, dz * s_own, 1.0f);
        }
    }
}

// ---------------- K4: combine + outputs, 8 lanes x NE=4 (non-persistent) ----
__global__ void __launch_bounds__(128) k_final(
        const float* __restrict__ pos,
        const float* __restrict__ comb_w1, const float* __restrict__ cb1,
        const float* __restrict__ comb_w2, const float* __restrict__ cb2,
        float* __restrict__ outx, float* __restrict__ outp) {
    __shared__ __align__(16) float sW1[64 * 32];
    __shared__ __align__(16) float sW2[32 * 32];
    int tid = threadIdx.x;
    for (int k = tid; k < 2048; k += 128) sW1[k] = comb_w1[k];
    for (int k = tid; k < 1024; k += 128) sW2[k] = comb_w2[k];
    __syncthreads();

    int q = tid & 7;
    int c0 = q * 4;
    int n0 = blockIdx.x * 64 + (tid >> 3) * 4;
    if (n0 >= N_NODES) return;   // warp-uniform
    int half = (q & 3) * 8;

    float inA[8], inB[8], inC[8], inD[8];
    {
        const float* src = (q < 4) ? &g_xm[n0 * 32] : &g_macc[n0 * 32];
        float4 v0 = *(const float4*)&src[half];
        float4 v1 = *(const float4*)&src[half + 4];
        inA[0] = v0.x; inA[1] = v0.y; inA[2] = v0.z; inA[3] = v0.w;
        inA[4] = v1.x; inA[5] = v1.y; inA[6] = v1.z; inA[7] = v1.w;
    }
    {
        const float* src = (q < 4) ? &g_xm[(n0 + 1) * 32] : &g_macc[(n0 + 1) * 32];
        float4 v0 = *(const float4*)&src[half];
        float4 v1 = *(const float4*)&src[half + 4];
        inB[0] = v0.x; inB[1] = v0.y; inB[2] = v0.z; inB[3] = v0.w;
        inB[4] = v1.x; inB[5] = v1.y; inB[6] = v1.z; inB[7] = v1.w;
    }
    {
        const float* src = (q < 4) ? &g_xm[(n0 + 2) * 32] : &g_macc[(n0 + 2) * 32];
        float4 v0 = *(const float4*)&src[half];
        float4 v1 = *(const float4*)&src[half + 4];
        inC[0] = v0.x; inC[1] = v0.y; inC[2] = v0.z; inC[3] = v0.w;
        inC[4] = v1.x; inC[5] = v1.y; inC[6] = v1.z; inC[7] = v1.w;
    }
    {
        const float* src = (q < 4) ? &g_xm[(n0 + 3) * 32] : &g_macc[(n0 + 3) * 32];
        float4 v0 = *(const float4*)&src[half];
        float4 v1 = *(const float4*)&src[half + 4];
        inD[0] = v0.x; inD[1] = v0.y; inD[2] = v0.z; inD[3] = v0.w;
        inD[4] = v1.x; inD[5] = v1.y; inD[6] = v1.z; inD[7] = v1.w;
    }

    u64 accA[2], accB[2], accC[2], accD[2];
    {
        u64 b0 = pack2(cb1[c0], cb1[c0 + 1]);
        u64 b1 = pack2(cb1[c0 + 2], cb1[c0 + 3]);
        accA[0] = b0; accA[1] = b1; accB[0] = b0; accB[1] = b1;
        accC[0] = b0; accC[1] = b1; accD[0] = b0; accD[1] = b1;
    }
    #pragma unroll
    for (int kk = 0; kk < 64; kk++) {
        float vA = __shfl_sync(0xffffffffu, inA[kk & 7], kk >> 3, 8);
        float vB = __shfl_sync(0xffffffffu, inB[kk & 7], kk >> 3, 8);
        float vC = __shfl_sync(0xffffffffu, inC[kk & 7], kk >> 3, 8);
        float vD = __shfl_sync(0xffffffffu, inD[kk & 7], kk >> 3, 8);
        u64 vvA = pack2(vA, vA), vvB = pack2(vB, vB);
        u64 vvC = pack2(vC, vC), vvD = pack2(vD, vD);
        ulonglong2 w = *(const ulonglong2*)&sW1[kk * 32 + c0];
        ffma2(accA[0], w.x, vvA); ffma2(accA[1], w.y, vvA);
        ffma2(accB[0], w.x, vvB); ffma2(accB[1], w.y, vvB);
        ffma2(accC[0], w.x, vvC); ffma2(accC[1], w.y, vvC);
        ffma2(accD[0], w.x, vvD); ffma2(accD[1], w.y, vvD);
    }
    float hhA[4], hhB[4], hhC[4], hhD[4];
    {
        float t0, t1;
        unpack2(accA[0], t0, t1); hhA[0] = siluf(t0); hhA[1] = siluf(t1);
        unpack2(accA[1], t0, t1); hhA[2] = siluf(t0); hhA[3] = siluf(t1);
        unpack2(accB[0], t0, t1); hhB[0] = siluf(t0); hhB[1] = siluf(t1);
        unpack2(accB[1], t0, t1); hhB[2] = siluf(t0); hhB[3] = siluf(t1);
        unpack2(accC[0], t0, t1); hhC[0] = siluf(t0); hhC[1] = siluf(t1);
        unpack2(accC[1], t0, t1); hhC[2] = siluf(t0); hhC[3] = siluf(t1);
        unpack2(accD[0], t0, t1); hhD[0] = siluf(t0); hhD[1] = siluf(t1);
        unpack2(accD[1], t0, t1); hhD[2] = siluf(t0); hhD[3] = siluf(t1);
    }

    u64 a2A[2], a2B[2], a2C[2], a2D[2];
    {
        u64 b0 = pack2(cb2[c0], cb2[c0 + 1]);
        u64 b1 = pack2(cb2[c0 + 2], cb2[c0 + 3]);
        a2A[0] = b0; a2A[1] = b1; a2B[0] = b0; a2B[1] = b1;
        a2C[0] = b0; a2C[1] = b1; a2D[0] = b0; a2D[1] = b1;
    }
    MV32X4(a2A, a2B, a2C, a2D, hhA, hhB, hhC, hhD, sW2, c0);

    {
        float t0, t1, t2, t3;
        unpack2(a2A[0], t0, t1); unpack2(a2A[1], t2, t3);
        float4 xm = *(const float4*)&g_xm[n0 * 32 + c0];
        *(float4*)&outx[n0 * 32 + c0] = make_float4(
            siluf(xm.x + t0), siluf(xm.y + t1), siluf(xm.z + t2), siluf(xm.w + t3));
    }
    {
        int n = n0 + 1;
        float t0, t1, t2, t3;
        unpack2(a2B[0], t0, t1); unpack2(a2B[1], t2, t3);
        float4 xm = *(const float4*)&g_xm[n * 32 + c0];
        *(float4*)&outx[n * 32 + c0] = make_float4(
            siluf(xm.x + t0), siluf(xm.y + t1), siluf(xm.z + t2), siluf(xm.w + t3));
    }
    {
        int n = n0 + 2;
        float t0, t1, t2, t3;
        unpack2(a2C[0], t0, t1); unpack2(a2C[1], t2, t3);
        float4 xm = *(const float4*)&g_xm[n * 32 + c0];
        *(float4*)&outx[n * 32 + c0] = make_float4(
            siluf(xm.x + t0), siluf(xm.y + t1), siluf(xm.z + t2), siluf(xm.w + t3));
    }
    {
        int n = n0 + 3;
        float t0, t1, t2, t3;
        unpack2(a2D[0], t0, t1); unpack2(a2D[1], t2, t3);
        float4 xm = *(const float4*)&g_xm[n * 32 + c0];
        *(float4*)&outx[n * 32 + c0] = make_float4(
            siluf(xm.x + t0), siluf(xm.y + t1), siluf(xm.z + t2), siluf(xm.w + t3));
    }

    if (q < 4) {
        int n = n0 + q;
        float4 pa = *(const float4*)&g_pacc[n * 4];
        float ic = 1.0f / fmaxf(pa.w, 1.0f);
        outp[n * 3 + 0] = pos[n * 3 + 0] + pa.x * ic;
        outp[n * 3 + 1] = pos[n * 3 + 1] + pa.y * ic;
        outp[n * 3 + 2] = pos[n * 3 + 2] + pa.z * ic;
    }
}

// ---------------- launch ----------------
static int s_sm_count = 0;
static int s_blk_edge = 0;

extern "C" void kernel_launch(void* const* d_in, const int* in_sizes, int n_in,
                              void* d_out, int out_size) {
    const float* x        = (const float*)d_in[0];
    const int*   ei       = (const int*)d_in[1];
    const float* pos      = (const float*)d_in[2];
    const float* time     = (const float*)d_in[3];
    const int*   batch    = (const int*)d_in[4];
    const float* means    = (const float*)d_in[5];
    const float* betas    = (const float*)d_in[6];
    const float* w_dist   = (const float*)d_in[7];
    const float* msg_w1   = (const float*)d_in[8];
    const float* msg_b1   = (const float*)d_in[9];
    const float* msg_w2   = (const float*)d_in[10];
    const float* msg_b2   = (const float*)d_in[11];
    const float* gate_w   = (const float*)d_in[12];
    const float* gate_b   = (const float*)d_in[13];
    const float* time_w1  = (const float*)d_in[14];
    const float* time_b1  = (const float*)d_in[15];
    const float* time_w2  = (const float*)d_in[16];
    const float* time_b2  = (const float*)d_in[17];
    const float* comb_w1  = (const float*)d_in[18];
    const float* comb_b1  = (const float*)d_in[19];
    const float* comb_w2  = (const float*)d_in[20];
    const float* comb_b2  = (const float*)d_in[21];
    const float* coord_w1 = (const float*)d_in[22];
    const float* coord_b1 = (const float*)d_in[23];
    const float* coord_w2 = (const float*)d_in[24];
    const float* coord_b2 = (const float*)d_in[25];

    float* outx = (float*)d_out;
    float* outp = (float*)d_out + N_NODES * 32;

    if (s_sm_count == 0) {
        cudaDeviceGetAttribute(&s_sm_count, cudaDevAttrMultiProcessorCount, 0);
        int b;
        cudaOccupancyMaxActiveBlocksPerMultiprocessor(&b, k_edge, 128, 0);
        s_blk_edge = b > 0 ? b : 4;
    }
    int ge = s_sm_count * s_blk_edge;
    if (ge > EDGE_TILES) ge = EDGE_TILES;

    k_time<<<G_GRAPHS / 4 + TAB / 8, 256>>>(time, time_w1, time_b1, time_w2, time_b2,
                                            means, betas, w_dist);
    k_node<<<NODE_BLOCKS, 128>>>(x, batch, pos, msg_w1, msg_b1, gate_w, gate_b);
    k_edge<<<ge, 128>>>(ei, msg_w2, msg_b2,
                        coord_w1, coord_b1, coord_w2, coord_b2);
    k_final<<<NODE_BLOCKS, 128>>>(pos, comb_w1, comb_b1, comb_w2, comb_b2,
                                  outx, outp);
}